// round 11
// baseline (speedup 1.0000x reference)
#include <cuda_runtime.h>
#include <cuda_bf16.h>
#include <math.h>
#include <stdint.h>

#define NSAMP  131072
#define NDIM   512
#define NCOMP  256
#define NCLASS 8
#define NBIN   100

// ---------------- scratch (__device__ globals; device-code access ONLY) ----
__device__ float         g_data0[(size_t)NSAMP * NCOMP];   // data0 -> delta
__device__ __nv_bfloat16 g_B1[(size_t)NCOMP * 3 * NDIM];   // 256 x 1536 aug wT^T
__device__ __nv_bfloat16 g_B2[(size_t)NDIM * 3 * NCOMP];   // 512 x 768  aug wT
__device__ float g_ktx[NCLASS * NBIN * NCOMP];             // knots [c][t][j]
__device__ float g_kty[NCLASS * NBIN * NCOMP];
__device__ float g_ktd[NCLASS * NBIN * NCOMP];
__device__ int   g_idx[NSAMP];
__device__ int   g_cnt[NCLASS];
__device__ int   g_cur[NCLASS];

// ---------------- helpers ---------------------------------------------------
__device__ __forceinline__ void cp16(void* s, const void* g) {
    uint32_t sa = (uint32_t)__cvta_generic_to_shared(s);
    asm volatile("cp.async.ca.shared.global [%0], [%1], 16;" :: "r"(sa), "l"(g));
}
#define CP_COMMIT() asm volatile("cp.async.commit_group;" ::: "memory")
#define CP_WAIT0()  asm volatile("cp.async.wait_group 0;" ::: "memory")

__device__ __forceinline__ void mma16(float* c, const uint32_t* a, const uint32_t* b) {
    asm volatile(
        "mma.sync.aligned.m16n8k16.row.col.f32.bf16.bf16.f32 "
        "{%0,%1,%2,%3}, {%4,%5,%6,%7}, {%8,%9}, {%0,%1,%2,%3};"
        : "+f"(c[0]), "+f"(c[1]), "+f"(c[2]), "+f"(c[3])
        : "r"(a[0]), "r"(a[1]), "r"(a[2]), "r"(a[3]), "r"(b[0]), "r"(b[1]));
}

// k16 in-segment permutation: fragment pairs (k=2lc,2lc+1,2lc+8,2lc+9) become
// 4 consecutive bf16 -> one LDS.64 per fragment.
__host__ __device__ __forceinline__ int permj(int j) {
    return ((j & 7) >> 1) * 4 + ((j >> 3) << 1) + (j & 1);
}

// ---------------- prep: wT -> augmented 3xBF16 operand layouts -------------
__global__ void prep_wt(const float* __restrict__ wT) {
    int e = blockIdx.x * 256 + threadIdx.x;    // over 512*256
    int r = e >> 8, c = e & 255;               // r: dim, c: comp
    float v  = wT[e];
    __nv_bfloat16 hi = __float2bfloat16_rn(v);
    __nv_bfloat16 lo = __float2bfloat16_rn(v - __bfloat162float(hi));
    {   // B1 row n=c (comp), k=r (dim)
        size_t base = (size_t)c * 1536 + (r >> 4) * 48 + permj(r & 15);
        g_B1[base] = hi; g_B1[base + 16] = hi; g_B1[base + 32] = lo;
    }
    {   // B2 row n=r (dim), k=c (comp)
        size_t base = (size_t)r * 768 + (c >> 4) * 48 + permj(c & 15);
        g_B2[base] = hi; g_B2[base + 16] = hi; g_B2[base + 32] = lo;
    }
}

// knots [c][j][t] -> [c][t][j]
__global__ void prep_knots(const float* __restrict__ kx, const float* __restrict__ ky,
                           const float* __restrict__ kd) {
    int e = blockIdx.x * 256 + threadIdx.x;    // 8*100*256
    int c = e / (NBIN * NCOMP);
    int rem = e - c * NBIN * NCOMP;
    int t = rem >> 8, j = rem & 255;
    int src = (c * NCOMP + j) * NBIN + t;
    g_ktx[e] = kx[src]; g_kty[e] = ky[src]; g_ktd[e] = kd[src];
}

// class sort
__global__ void prep_zero() {
    if (threadIdx.x < NCLASS) { g_cnt[threadIdx.x] = 0; g_cur[threadIdx.x] = 0; }
}
__global__ void prep_count(const int* __restrict__ label) {
    __shared__ int h[NCLASS];
    if (threadIdx.x < NCLASS) h[threadIdx.x] = 0;
    __syncthreads();
    atomicAdd(&h[label[blockIdx.x * 256 + threadIdx.x]], 1);
    __syncthreads();
    if (threadIdx.x < NCLASS) atomicAdd(&g_cnt[threadIdx.x], h[threadIdx.x]);
}
__global__ void prep_scatter(const int* __restrict__ label) {
    __shared__ int h[NCLASS], base[NCLASS], off[NCLASS];
    if (threadIdx.x < NCLASS) h[threadIdx.x] = 0;
    __syncthreads();
    int i = blockIdx.x * 256 + threadIdx.x;
    int c = label[i];
    int r = atomicAdd(&h[c], 1);               // intra-block rank
    __syncthreads();
    if (threadIdx.x < NCLASS) {
        base[threadIdx.x] = atomicAdd(&g_cur[threadIdx.x], h[threadIdx.x]);
        int o = 0;
        #pragma unroll
        for (int cc = 0; cc < NCLASS; ++cc) if (cc < threadIdx.x) o += g_cnt[cc];
        off[threadIdx.x] = o;
    }
    __syncthreads();
    g_idx[off[c] + base[c] + r] = i;
}

// ---------------- GEMM staging (512 threads) --------------------------------
#define ASTRIDE 48            // bf16 units; 96B rows
#define BSTRIDE_S 48
#define NTHR 512

template<int LDA>
__device__ __forceinline__ void ldgA(const float* __restrict__ Ag, int m0, int ci,
                                     int tid, float4* a_src) {
    int row = tid >> 2, fi = tid & 3;          // 128 rows x 4 float4
    a_src[0] = *(const float4*)&Ag[(size_t)(m0 + row) * LDA + ci * 16 + fi * 4];
}
// A segs: [hi, lo, hi]
__device__ __forceinline__ void stsA(__nv_bfloat16* __restrict__ Ab, int tid,
                                     const float4* a_src) {
    int row = tid >> 2, fi = tid & 3;
    const float* v = (const float*)&a_src[0];
    #pragma unroll
    for (int hpair = 0; hpair < 2; ++hpair) {
        int j0 = fi * 4 + hpair * 2;           // even -> permj(j0+1)==permj(j0)+1
        float v0 = v[hpair * 2], v1 = v[hpair * 2 + 1];
        __nv_bfloat16 h0 = __float2bfloat16_rn(v0);
        __nv_bfloat16 h1 = __float2bfloat16_rn(v1);
        __nv_bfloat16 l0 = __float2bfloat16_rn(v0 - __bfloat162float(h0));
        __nv_bfloat16 l1 = __float2bfloat16_rn(v1 - __bfloat162float(h1));
        int p = row * ASTRIDE + permj(j0);
        *(__nv_bfloat162*)&Ab[p]      = __nv_bfloat162(h0, h1);
        *(__nv_bfloat162*)&Ab[p + 16] = __nv_bfloat162(l0, l1);
        *(__nv_bfloat162*)&Ab[p + 32] = __nv_bfloat162(h0, h1);
    }
}
// coalesced: 6 consecutive threads cover one row's 96B chunk (6 x 16B)
template<int BSTR>
__device__ __forceinline__ void cpB(const __nv_bfloat16* __restrict__ Bg, int n0,
                                    int ci, int tid, __nv_bfloat16* __restrict__ Bb) {
    #pragma unroll
    for (int idx = tid; idx < 256 * 6; idx += NTHR) {
        int row = idx / 6, f = idx - row * 6;
        cp16(&Bb[row * BSTRIDE_S + f * 8],
             &Bg[(size_t)(n0 + row) * BSTR + ci * 48 + f * 8]);
    }
}

// ---------------- main GEMM (128x256 CTA tile, 16 warps, 64x32 warp tile) --
// EPI=1: g_data0[M,256] = data @ wT           (A=data,    B=g_B1, C=g_data0)
// EPI=2: out[M,512]     = data + delta @ wT^T (A=g_data0, B=g_B2, C=out)
template<int NCH, int BSTR, int LDA, int EPI>
__global__ __launch_bounds__(NTHR, 1)
void gemm_k(const float* __restrict__ Adat, const float* __restrict__ Dg,
            float* __restrict__ Cg)
{
    constexpr int NTN = 4;                     // 4 x n8 = 32 cols per warp
    constexpr int ASZ = 128 * ASTRIDE;
    constexpr int BSZ = 256 * BSTRIDE_S;
    constexpr int SSZ = ASZ + BSZ;
    extern __shared__ __nv_bfloat16 smb[];
    __nv_bfloat16* Abuf[2] = { smb, smb + SSZ };
    __nv_bfloat16* Bbuf[2] = { smb + ASZ, smb + SSZ + ASZ };

    const int tid = threadIdx.x, lane = tid & 31, wid = tid >> 5;
    const int lr = lane >> 2, lc = lane & 3;
    const int m0 = blockIdx.x * 128;
    const int n0 = blockIdx.y * 256;
    const int mw = (wid >> 3) * 64;            // 2 warp-rows x 64
    const int nw = (wid & 7) * 32;             // 8 warp-cols x 32

    const float*         Ag = (EPI == 1) ? Adat : (const float*)g_data0;
    const __nv_bfloat16* Bg = (EPI == 1) ? g_B1 : g_B2;
    float*               Cp = (EPI == 1) ? (float*)g_data0 : Cg;

    float acc[4][NTN][4];
    #pragma unroll
    for (int mi = 0; mi < 4; ++mi)
        #pragma unroll
        for (int ni = 0; ni < NTN; ++ni)
            #pragma unroll
            for (int q = 0; q < 4; ++q) acc[mi][ni][q] = 0.f;

    float4 a_src[1];

    cpB<BSTR>(Bg, n0, 0, tid, Bbuf[0]);
    CP_COMMIT();
    ldgA<LDA>(Ag, m0, 0, tid, a_src);
    stsA(Abuf[0], tid, a_src);
    CP_WAIT0();
    __syncthreads();

    for (int ci = 0; ci < NCH; ++ci) {
        const int cur = ci & 1, nxt = cur ^ 1;
        if (ci + 1 < NCH) {
            cpB<BSTR>(Bg, n0, ci + 1, tid, Bbuf[nxt]);
            CP_COMMIT();
            ldgA<LDA>(Ag, m0, ci + 1, tid, a_src);
        }
        const __nv_bfloat16* Ab = Abuf[cur];
        const __nv_bfloat16* Bb = Bbuf[cur];
        #pragma unroll
        for (int seg = 0; seg < 3; ++seg) {    // A:[hi,lo,hi] x B:[hi,hi,lo]
            uint2 bf[NTN];
            #pragma unroll
            for (int ni = 0; ni < NTN; ++ni)
                bf[ni] = *(const uint2*)&Bb[(nw + ni * 8 + lr) * BSTRIDE_S + seg * 16 + lc * 4];
            #pragma unroll
            for (int mi = 0; mi < 4; ++mi) {
                int ar = mw + mi * 16 + lr;
                uint2 aA = *(const uint2*)&Ab[ar * ASTRIDE + seg * 16 + lc * 4];
                uint2 aB = *(const uint2*)&Ab[(ar + 8) * ASTRIDE + seg * 16 + lc * 4];
                uint32_t a[4] = { aA.x, aB.x, aA.y, aB.y };
                #pragma unroll
                for (int ni = 0; ni < NTN; ++ni)
                    mma16(acc[mi][ni], a, (const uint32_t*)&bf[ni]);
            }
        }
        if (ci + 1 < NCH) { stsA(Abuf[nxt], tid, a_src); CP_WAIT0(); }
        __syncthreads();
    }

    #pragma unroll
    for (int mi = 0; mi < 4; ++mi) {
        int r0 = m0 + mw + mi * 16 + lr;
        #pragma unroll
        for (int ni = 0; ni < NTN; ++ni) {
            int cc = n0 + nw + ni * 8 + 2 * lc;
            if (EPI == 1) {
                *(float2*)&Cp[(size_t)r0 * NCOMP + cc] =
                    make_float2(acc[mi][ni][0], acc[mi][ni][1]);
                *(float2*)&Cp[(size_t)(r0 + 8) * NCOMP + cc] =
                    make_float2(acc[mi][ni][2], acc[mi][ni][3]);
            } else {
                float2 d0 = *(const float2*)&Dg[(size_t)r0 * NDIM + cc];
                float2 d1 = *(const float2*)&Dg[(size_t)(r0 + 8) * NDIM + cc];
                *(float2*)&Cp[(size_t)r0 * NDIM + cc] =
                    make_float2(acc[mi][ni][0] + d0.x, acc[mi][ni][1] + d0.y);
                *(float2*)&Cp[(size_t)(r0 + 8) * NDIM + cc] =
                    make_float2(acc[mi][ni][2] + d1.x, acc[mi][ni][3] + d1.y);
            }
        }
    }
}

// ---------------- spline: class-sorted, smem tables, lane=comp -------------
#define SPB 128                                // blocks per class
__global__ __launch_bounds__(256) void spline_kernel(float* __restrict__ logj)
{
    __shared__ float xs[NBIN * 32], ys[NBIN * 32], ds[NBIN * 32];
    __shared__ float acc_s[1024];
    const int tid = threadIdx.x, lane = tid & 31, wid = tid >> 5;
    const int c = blockIdx.x / SPB, b = blockIdx.x % SPB;
    const int cnt = g_cnt[c];
    int off = 0;
    #pragma unroll
    for (int cc = 0; cc < NCLASS; ++cc) if (cc < c) off += g_cnt[cc];
    const int chunk = (cnt + SPB - 1) / SPB;
    const int s0 = b * chunk;
    const int s1 = min(s0 + chunk, cnt);
    const int nloc = s1 - s0;
    if (nloc <= 0) return;
    for (int i = tid; i < nloc; i += 256) acc_s[i] = 0.f;

    for (int tile = 0; tile < 8; ++tile) {
        __syncthreads();
        const int j0 = tile * 32;
        for (int e = tid; e < NBIN * 32; e += 256) {
            int t = e >> 5, j = e & 31;
            int gi = (c * NBIN + t) * NCOMP + j0 + j;
            xs[e] = g_ktx[gi]; ys[e] = g_kty[gi]; ds[e] = g_ktd[gi];
        }
        __syncthreads();

        for (int i = s0 + wid; i < s1; i += 8) {
            const int s = g_idx[off + i];
            const size_t gi = (size_t)s * NCOMP + j0 + lane;
            const float x = g_data0[gi];
            int id = 0;
            #pragma unroll
            for (int stp = 64; stp >= 1; stp >>= 1) {
                int t = id + stp;
                int ta = min(t, NBIN);
                float kv = xs[(ta - 1) * 32 + lane];
                if (t <= NBIN && kv < x) id = t;
            }
            int k = min(max(id - 1, 0), NBIN - 2);
            float x0 = xs[k * 32 + lane], x1 = xs[(k + 1) * 32 + lane];
            float y0 = ys[k * 32 + lane], y1 = ys[(k + 1) * 32 + lane];
            float da = ds[k * 32 + lane], db = ds[(k + 1) * 32 + lane];
            float w  = x1 - x0, dy = y1 - y0;
            float iw = __fdividef(1.f, w);
            float sv = dy * iw;
            float xi = fminf(fmaxf((x - x0) * iw, 0.f), 1.f);
            float xi1 = 1.f - xi;
            float denom = sv + (da + db - 2.f * sv) * xi * xi1;
            float idn = __fdividef(1.f, denom);
            float y_in = y0 + dy * (sv * xi * xi + da * xi * xi1) * idn;
            float num  = db * xi * xi + 2.f * sv * xi * xi1 + da * xi1 * xi1;
            bool below = (id == 0), above = (id == NBIN);
            float arg = below ? da : (above ? db : sv * sv * num * idn * idn);
            float y   = below ? (y0 + da * (x - x0))
                              : (above ? (y1 + db * (x - x1)) : y_in);
            float ld  = __logf(arg);
            g_data0[gi] = y - x;
            #pragma unroll
            for (int o = 16; o; o >>= 1) ld += __shfl_down_sync(0xFFFFFFFFu, ld, o);
            if (lane == 0) acc_s[i - s0] += ld;
        }
    }
    __syncthreads();
    for (int i = tid; i < nloc; i += 256)
        logj[g_idx[off + s0 + i]] = acc_s[i];
}

// ---------------- launch ----------------------------------------------------
// gemm1 stays the 4th launch -> lands on ncu's capture slot.
extern "C" void kernel_launch(void* const* d_in, const int* in_sizes, int n_in,
                              void* d_out, int out_size) {
    const float* data  = (const float*)d_in[0];
    const float* wT    = (const float*)d_in[1];
    const float* kx    = (const float*)d_in[2];
    const float* ky    = (const float*)d_in[3];
    const float* kd    = (const float*)d_in[4];
    const int*   label = (const int*)d_in[5];

    float* out  = (float*)d_out;                    // (N, NDIM)
    float* logj = out + (size_t)NSAMP * NDIM;       // (N,)

    constexpr int SMG = 2 * (128 * ASTRIDE + 256 * BSTRIDE_S) * 2;  // 72 KB
    cudaFuncSetAttribute((const void*)gemm_k<32, 1536, 512, 1>,
                         cudaFuncAttributeMaxDynamicSharedMemorySize, SMG);
    cudaFuncSetAttribute((const void*)gemm_k<16, 768, 256, 2>,
                         cudaFuncAttributeMaxDynamicSharedMemorySize, SMG);

    prep_wt<<<NDIM * NCOMP / 256, 256>>>(wT);
    prep_knots<<<NCLASS * NBIN * NCOMP / 256, 256>>>(kx, ky, kd);
    prep_zero<<<1, 32>>>();

    gemm_k<32, 1536, 512, 1><<<dim3(NSAMP / 128, 1), NTHR, SMG>>>(
        data, nullptr, nullptr);

    prep_count<<<NSAMP / 256, 256>>>(label);
    prep_scatter<<<NSAMP / 256, 256>>>(label);

    spline_kernel<<<NCLASS * SPB, 256>>>(logj);

    gemm_k<16, 768, 256, 2><<<dim3(NSAMP / 128, NDIM / 256), NTHR, SMG>>>(
        nullptr, data, out);
}

// round 12
// speedup vs baseline: 1.1614x; 1.1614x over previous
#include <cuda_runtime.h>
#include <cuda_bf16.h>
#include <math.h>
#include <stdint.h>

#define NSAMP  131072
#define NDIM   512
#define NCOMP  256
#define NCLASS 8
#define NBIN   100

// ---------------- scratch (__device__ globals; device-code access ONLY) ----
__device__ float         g_data0[(size_t)NSAMP * NCOMP];   // data0 -> delta
__device__ __nv_bfloat16 g_B1[(size_t)NCOMP * 3 * NDIM];   // 256 x 1536 aug wT^T
__device__ __nv_bfloat16 g_B2[(size_t)NDIM * 3 * NCOMP];   // 512 x 768  aug wT
__device__ float g_ktx[NCLASS * NBIN * NCOMP];             // knots [c][t][j]
__device__ float g_kty[NCLASS * NBIN * NCOMP];
__device__ float g_ktd[NCLASS * NBIN * NCOMP];
__device__ int   g_idx[NSAMP];
__device__ int   g_cnt[NCLASS];
__device__ int   g_cur[NCLASS];

// ---------------- helpers ---------------------------------------------------
__device__ __forceinline__ void cp16(void* s, const void* g) {
    uint32_t sa = (uint32_t)__cvta_generic_to_shared(s);
    asm volatile("cp.async.ca.shared.global [%0], [%1], 16;" :: "r"(sa), "l"(g));
}
#define CP_COMMIT() asm volatile("cp.async.commit_group;" ::: "memory")
#define CP_WAIT0()  asm volatile("cp.async.wait_group 0;" ::: "memory")

__device__ __forceinline__ void mma16(float* c, const uint32_t* a, const uint32_t* b) {
    asm volatile(
        "mma.sync.aligned.m16n8k16.row.col.f32.bf16.bf16.f32 "
        "{%0,%1,%2,%3}, {%4,%5,%6,%7}, {%8,%9}, {%0,%1,%2,%3};"
        : "+f"(c[0]), "+f"(c[1]), "+f"(c[2]), "+f"(c[3])
        : "r"(a[0]), "r"(a[1]), "r"(a[2]), "r"(a[3]), "r"(b[0]), "r"(b[1]));
}

// k16 in-segment permutation: fragment pairs (k=2lc,2lc+1,2lc+8,2lc+9) become
// 4 consecutive bf16 -> one LDS.64 per fragment.
__host__ __device__ __forceinline__ int permj(int j) {
    return ((j & 7) >> 1) * 4 + ((j >> 3) << 1) + (j & 1);
}

// ---------------- prep: wT -> augmented 3xBF16 operand layouts -------------
__global__ void prep_wt(const float* __restrict__ wT) {
    int e = blockIdx.x * 256 + threadIdx.x;    // over 512*256
    int r = e >> 8, c = e & 255;               // r: dim, c: comp
    float v  = wT[e];
    __nv_bfloat16 hi = __float2bfloat16_rn(v);
    __nv_bfloat16 lo = __float2bfloat16_rn(v - __bfloat162float(hi));
    {   // B1 row n=c (comp), k=r (dim)
        size_t base = (size_t)c * 1536 + (r >> 4) * 48 + permj(r & 15);
        g_B1[base] = hi; g_B1[base + 16] = hi; g_B1[base + 32] = lo;
    }
    {   // B2 row n=r (dim), k=c (comp)
        size_t base = (size_t)r * 768 + (c >> 4) * 48 + permj(c & 15);
        g_B2[base] = hi; g_B2[base + 16] = hi; g_B2[base + 32] = lo;
    }
}

// knots [c][j][t] -> [c][t][j]
__global__ void prep_knots(const float* __restrict__ kx, const float* __restrict__ ky,
                           const float* __restrict__ kd) {
    int e = blockIdx.x * 256 + threadIdx.x;    // 8*100*256
    int c = e / (NBIN * NCOMP);
    int rem = e - c * NBIN * NCOMP;
    int t = rem >> 8, j = rem & 255;
    int src = (c * NCOMP + j) * NBIN + t;
    g_ktx[e] = kx[src]; g_kty[e] = ky[src]; g_ktd[e] = kd[src];
}

// class sort
__global__ void prep_zero() {
    if (threadIdx.x < NCLASS) { g_cnt[threadIdx.x] = 0; g_cur[threadIdx.x] = 0; }
}
__global__ void prep_count(const int* __restrict__ label) {
    __shared__ int h[NCLASS];
    if (threadIdx.x < NCLASS) h[threadIdx.x] = 0;
    __syncthreads();
    atomicAdd(&h[label[blockIdx.x * 256 + threadIdx.x]], 1);
    __syncthreads();
    if (threadIdx.x < NCLASS) atomicAdd(&g_cnt[threadIdx.x], h[threadIdx.x]);
}
__global__ void prep_scatter(const int* __restrict__ label) {
    __shared__ int h[NCLASS], base[NCLASS], off[NCLASS];
    if (threadIdx.x < NCLASS) h[threadIdx.x] = 0;
    __syncthreads();
    int i = blockIdx.x * 256 + threadIdx.x;
    int c = label[i];
    int r = atomicAdd(&h[c], 1);               // intra-block rank
    __syncthreads();
    if (threadIdx.x < NCLASS) {
        base[threadIdx.x] = atomicAdd(&g_cur[threadIdx.x], h[threadIdx.x]);
        int o = 0;
        #pragma unroll
        for (int cc = 0; cc < NCLASS; ++cc) if (cc < threadIdx.x) o += g_cnt[cc];
        off[threadIdx.x] = o;
    }
    __syncthreads();
    g_idx[off[c] + base[c] + r] = i;
}

// ---------------- GEMM staging (256 threads, 128x128 CTA tile) --------------
#define ASTRIDE 48            // bf16 units; 96B rows
#define BSTRIDE_S 48
#define NTHR 256

template<int LDA>
__device__ __forceinline__ void ldgA(const float* __restrict__ Ag, int m0, int ci,
                                     int tid, float4* a_src) {
    #pragma unroll
    for (int i = 0; i < 2; ++i) {
        int idx = tid + i * 256;
        int row = idx >> 2, fi = idx & 3;
        a_src[i] = *(const float4*)&Ag[(size_t)(m0 + row) * LDA + ci * 16 + fi * 4];
    }
}
// A segs: [hi, lo, hi]
__device__ __forceinline__ void stsA(__nv_bfloat16* __restrict__ Ab, int tid,
                                     const float4* a_src) {
    #pragma unroll
    for (int i = 0; i < 2; ++i) {
        int idx = tid + i * 256;
        int row = idx >> 2, fi = idx & 3;
        const float* v = (const float*)&a_src[i];
        #pragma unroll
        for (int hpair = 0; hpair < 2; ++hpair) {
            int j0 = fi * 4 + hpair * 2;       // even -> permj(j0+1)==permj(j0)+1
            float v0 = v[hpair * 2], v1 = v[hpair * 2 + 1];
            __nv_bfloat16 h0 = __float2bfloat16_rn(v0);
            __nv_bfloat16 h1 = __float2bfloat16_rn(v1);
            __nv_bfloat16 l0 = __float2bfloat16_rn(v0 - __bfloat162float(h0));
            __nv_bfloat16 l1 = __float2bfloat16_rn(v1 - __bfloat162float(h1));
            int p = row * ASTRIDE + permj(j0);
            *(__nv_bfloat162*)&Ab[p]      = __nv_bfloat162(h0, h1);
            *(__nv_bfloat162*)&Ab[p + 16] = __nv_bfloat162(l0, l1);
            *(__nv_bfloat162*)&Ab[p + 32] = __nv_bfloat162(h0, h1);
        }
    }
}
// coalesced: 6 consecutive threads cover one row's 96B chunk (6 x 16B)
template<int BSTR>
__device__ __forceinline__ void cpB(const __nv_bfloat16* __restrict__ Bg, int n0,
                                    int ci, int tid, __nv_bfloat16* __restrict__ Bb) {
    #pragma unroll
    for (int i = 0; i < 3; ++i) {              // 128 rows * 6 = 768 transfers
        int idx = tid + i * 256;
        int row = idx / 6, f = idx - row * 6;
        cp16(&Bb[row * BSTRIDE_S + f * 8],
             &Bg[(size_t)(n0 + row) * BSTR + ci * 48 + f * 8]);
    }
}

// ---------------- main GEMM (128x128 CTA, 8 warps, 32x64 warp tile, 2 CTA/SM)
// EPI=1: g_data0[M,256] = data @ wT           (A=data,    B=g_B1, C=g_data0)
// EPI=2: out[M,512]     = data + delta @ wT^T (A=g_data0, B=g_B2, C=out)
template<int NCH, int BSTR, int LDA, int EPI>
__global__ __launch_bounds__(NTHR, 2)
void gemm_k(const float* __restrict__ Adat, const float* __restrict__ Dg,
            float* __restrict__ Cg)
{
    constexpr int NTN = 8;                     // 8 x n8 = 64 cols per warp
    constexpr int MI  = 2;                     // 2 x m16 = 32 rows per warp
    constexpr int ASZ = 128 * ASTRIDE;
    constexpr int BSZ = 128 * BSTRIDE_S;
    constexpr int SSZ = ASZ + BSZ;
    extern __shared__ __nv_bfloat16 smb[];
    __nv_bfloat16* Abuf[2] = { smb, smb + SSZ };
    __nv_bfloat16* Bbuf[2] = { smb + ASZ, smb + SSZ + ASZ };

    const int tid = threadIdx.x, lane = tid & 31, wid = tid >> 5;
    const int lr = lane >> 2, lc = lane & 3;
    const int m0 = blockIdx.x * 128;
    const int n0 = blockIdx.y * 128;
    const int mw = (wid >> 1) * 32;            // 4 warp-rows x 32
    const int nw = (wid & 1) * 64;             // 2 warp-cols x 64

    const float*         Ag = (EPI == 1) ? Adat : (const float*)g_data0;
    const __nv_bfloat16* Bg = (EPI == 1) ? g_B1 : g_B2;
    float*               Cp = (EPI == 1) ? (float*)g_data0 : Cg;

    float acc[MI][NTN][4];
    #pragma unroll
    for (int mi = 0; mi < MI; ++mi)
        #pragma unroll
        for (int ni = 0; ni < NTN; ++ni)
            #pragma unroll
            for (int q = 0; q < 4; ++q) acc[mi][ni][q] = 0.f;

    float4 a_src[2];

    cpB<BSTR>(Bg, n0, 0, tid, Bbuf[0]);
    CP_COMMIT();
    ldgA<LDA>(Ag, m0, 0, tid, a_src);
    stsA(Abuf[0], tid, a_src);
    CP_WAIT0();
    __syncthreads();

    for (int ci = 0; ci < NCH; ++ci) {
        const int cur = ci & 1, nxt = cur ^ 1;
        if (ci + 1 < NCH) {
            cpB<BSTR>(Bg, n0, ci + 1, tid, Bbuf[nxt]);
            CP_COMMIT();
            ldgA<LDA>(Ag, m0, ci + 1, tid, a_src);
        }
        const __nv_bfloat16* Ab = Abuf[cur];
        const __nv_bfloat16* Bb = Bbuf[cur];
        #pragma unroll
        for (int seg = 0; seg < 3; ++seg) {    // A:[hi,lo,hi] x B:[hi,hi,lo]
            uint2 bf[NTN];
            #pragma unroll
            for (int ni = 0; ni < NTN; ++ni)
                bf[ni] = *(const uint2*)&Bb[(nw + ni * 8 + lr) * BSTRIDE_S + seg * 16 + lc * 4];
            #pragma unroll
            for (int mi = 0; mi < MI; ++mi) {
                int ar = mw + mi * 16 + lr;
                uint2 aA = *(const uint2*)&Ab[ar * ASTRIDE + seg * 16 + lc * 4];
                uint2 aB = *(const uint2*)&Ab[(ar + 8) * ASTRIDE + seg * 16 + lc * 4];
                uint32_t a[4] = { aA.x, aB.x, aA.y, aB.y };
                #pragma unroll
                for (int ni = 0; ni < NTN; ++ni)
                    mma16(acc[mi][ni], a, (const uint32_t*)&bf[ni]);
            }
        }
        if (ci + 1 < NCH) { stsA(Abuf[nxt], tid, a_src); CP_WAIT0(); }
        __syncthreads();
    }

    #pragma unroll
    for (int mi = 0; mi < MI; ++mi) {
        int r0 = m0 + mw + mi * 16 + lr;
        #pragma unroll
        for (int ni = 0; ni < NTN; ++ni) {
            int cc = n0 + nw + ni * 8 + 2 * lc;
            if (EPI == 1) {
                *(float2*)&Cp[(size_t)r0 * NCOMP + cc] =
                    make_float2(acc[mi][ni][0], acc[mi][ni][1]);
                *(float2*)&Cp[(size_t)(r0 + 8) * NCOMP + cc] =
                    make_float2(acc[mi][ni][2], acc[mi][ni][3]);
            } else {
                float2 d0 = *(const float2*)&Dg[(size_t)r0 * NDIM + cc];
                float2 d1 = *(const float2*)&Dg[(size_t)(r0 + 8) * NDIM + cc];
                *(float2*)&Cp[(size_t)r0 * NDIM + cc] =
                    make_float2(acc[mi][ni][0] + d0.x, acc[mi][ni][1] + d0.y);
                *(float2*)&Cp[(size_t)(r0 + 8) * NDIM + cc] =
                    make_float2(acc[mi][ni][2] + d1.x, acc[mi][ni][3] + d1.y);
            }
        }
    }
}

// ---------------- spline: class-sorted, smem tables, lane=comp -------------
#define SPB 128                                // blocks per class
__global__ __launch_bounds__(256) void spline_kernel(float* __restrict__ logj)
{
    __shared__ float xs[NBIN * 32], ys[NBIN * 32], ds[NBIN * 32];
    __shared__ float acc_s[1024];
    const int tid = threadIdx.x, lane = tid & 31, wid = tid >> 5;
    const int c = blockIdx.x / SPB, b = blockIdx.x % SPB;
    const int cnt = g_cnt[c];
    int off = 0;
    #pragma unroll
    for (int cc = 0; cc < NCLASS; ++cc) if (cc < c) off += g_cnt[cc];
    const int chunk = (cnt + SPB - 1) / SPB;
    const int s0 = b * chunk;
    const int s1 = min(s0 + chunk, cnt);
    const int nloc = s1 - s0;
    if (nloc <= 0) return;
    for (int i = tid; i < nloc; i += 256) acc_s[i] = 0.f;

    for (int tile = 0; tile < 8; ++tile) {
        __syncthreads();
        const int j0 = tile * 32;
        for (int e = tid; e < NBIN * 32; e += 256) {
            int t = e >> 5, j = e & 31;
            int gi = (c * NBIN + t) * NCOMP + j0 + j;
            xs[e] = g_ktx[gi]; ys[e] = g_kty[gi]; ds[e] = g_ktd[gi];
        }
        __syncthreads();

        for (int i = s0 + wid; i < s1; i += 8) {
            const int s = g_idx[off + i];
            const size_t gi = (size_t)s * NCOMP + j0 + lane;
            const float x = g_data0[gi];
            int id = 0;
            #pragma unroll
            for (int stp = 64; stp >= 1; stp >>= 1) {
                int t = id + stp;
                int ta = min(t, NBIN);
                float kv = xs[(ta - 1) * 32 + lane];
                if (t <= NBIN && kv < x) id = t;
            }
            int k = min(max(id - 1, 0), NBIN - 2);
            float x0 = xs[k * 32 + lane], x1 = xs[(k + 1) * 32 + lane];
            float y0 = ys[k * 32 + lane], y1 = ys[(k + 1) * 32 + lane];
            float da = ds[k * 32 + lane], db = ds[(k + 1) * 32 + lane];
            float w  = x1 - x0, dy = y1 - y0;
            float iw = __fdividef(1.f, w);
            float sv = dy * iw;
            float xi = fminf(fmaxf((x - x0) * iw, 0.f), 1.f);
            float xi1 = 1.f - xi;
            float denom = sv + (da + db - 2.f * sv) * xi * xi1;
            float idn = __fdividef(1.f, denom);
            float y_in = y0 + dy * (sv * xi * xi + da * xi * xi1) * idn;
            float num  = db * xi * xi + 2.f * sv * xi * xi1 + da * xi1 * xi1;
            bool below = (id == 0), above = (id == NBIN);
            float arg = below ? da : (above ? db : sv * sv * num * idn * idn);
            float y   = below ? (y0 + da * (x - x0))
                              : (above ? (y1 + db * (x - x1)) : y_in);
            float ld  = __logf(arg);
            g_data0[gi] = y - x;
            #pragma unroll
            for (int o = 16; o; o >>= 1) ld += __shfl_down_sync(0xFFFFFFFFu, ld, o);
            if (lane == 0) acc_s[i - s0] += ld;
        }
    }
    __syncthreads();
    for (int i = tid; i < nloc; i += 256)
        logj[g_idx[off + s0 + i]] = acc_s[i];
}

// ---------------- launch ----------------------------------------------------
// gemm1 stays the 4th launch -> lands on ncu's capture slot.
extern "C" void kernel_launch(void* const* d_in, const int* in_sizes, int n_in,
                              void* d_out, int out_size) {
    const float* data  = (const float*)d_in[0];
    const float* wT    = (const float*)d_in[1];
    const float* kx    = (const float*)d_in[2];
    const float* ky    = (const float*)d_in[3];
    const float* kd    = (const float*)d_in[4];
    const int*   label = (const int*)d_in[5];

    float* out  = (float*)d_out;                    // (N, NDIM)
    float* logj = out + (size_t)NSAMP * NDIM;       // (N,)

    constexpr int SMG = 2 * (128 * ASTRIDE + 128 * BSTRIDE_S) * 2;  // 48 KB
    cudaFuncSetAttribute((const void*)gemm_k<32, 1536, 512, 1>,
                         cudaFuncAttributeMaxDynamicSharedMemorySize, SMG);
    cudaFuncSetAttribute((const void*)gemm_k<16, 768, 256, 2>,
                         cudaFuncAttributeMaxDynamicSharedMemorySize, SMG);

    prep_wt<<<NDIM * NCOMP / 256, 256>>>(wT);
    prep_knots<<<NCLASS * NBIN * NCOMP / 256, 256>>>(kx, ky, kd);
    prep_zero<<<1, 32>>>();

    gemm_k<32, 1536, 512, 1><<<dim3(NSAMP / 128, NCOMP / 128), NTHR, SMG>>>(
        data, nullptr, nullptr);

    prep_count<<<NSAMP / 256, 256>>>(label);
    prep_scatter<<<NSAMP / 256, 256>>>(label);

    spline_kernel<<<NCLASS * SPB, 256>>>(logj);

    gemm_k<16, 768, 256, 2><<<dim3(NSAMP / 128, NDIM / 128), NTHR, SMG>>>(
        nullptr, data, out);
}

// round 14
// speedup vs baseline: 1.2482x; 1.0748x over previous
#include <cuda_runtime.h>
#include <cuda_bf16.h>
#include <math.h>
#include <stdint.h>

#define NSAMP  131072
#define NDIM   512
#define NCOMP  256
#define NCLASS 8
#define NBIN   100

// ---------------- scratch (__device__ globals; device-code access ONLY) ----
__device__ float         g_data0[(size_t)NSAMP * NCOMP];   // data0 -> delta
__device__ __nv_bfloat16 g_B1[(size_t)NCOMP * 2 * NDIM];   // 256 x 1024 [hi|lo] wT^T
__device__ __nv_bfloat16 g_B2[(size_t)NDIM * 2 * NCOMP];   // 512 x 512  [hi|lo] wT
__device__ float g_ktx[NCLASS * NBIN * NCOMP];             // knots [c][t][j]
__device__ float g_kty[NCLASS * NBIN * NCOMP];
__device__ float g_ktd[NCLASS * NBIN * NCOMP];
__device__ int   g_idx[NSAMP];
__device__ int   g_cnt[NCLASS];
__device__ int   g_cur[NCLASS];

// ---------------- helpers ---------------------------------------------------
__device__ __forceinline__ void cp16(void* s, const void* g) {
    uint32_t sa = (uint32_t)__cvta_generic_to_shared(s);
    asm volatile("cp.async.ca.shared.global [%0], [%1], 16;" :: "r"(sa), "l"(g));
}
#define CP_COMMIT() asm volatile("cp.async.commit_group;" ::: "memory")
#define CP_WAIT0()  asm volatile("cp.async.wait_group 0;" ::: "memory")

__device__ __forceinline__ void mma16(float* c, const uint32_t* a, const uint32_t* b) {
    asm volatile(
        "mma.sync.aligned.m16n8k16.row.col.f32.bf16.bf16.f32 "
        "{%0,%1,%2,%3}, {%4,%5,%6,%7}, {%8,%9}, {%0,%1,%2,%3};"
        : "+f"(c[0]), "+f"(c[1]), "+f"(c[2]), "+f"(c[3])
        : "r"(a[0]), "r"(a[1]), "r"(a[2]), "r"(a[3]), "r"(b[0]), "r"(b[1]));
}

// k16 in-segment permutation: fragment pairs (k=2lc,2lc+1,2lc+8,2lc+9) become
// 4 consecutive bf16 -> one LDS.64 per fragment.
__host__ __device__ __forceinline__ int permj(int j) {
    return ((j & 7) >> 1) * 4 + ((j >> 3) << 1) + (j & 1);
}

// ---------------- prep: wT -> [hi|lo] bf16 operand layouts ------------------
// Per 16 source k: 32 bf16 = [hi(16, permuted) | lo(16, permuted)].
// Products evaluated as aH*bH + aL*bH + aH*bL (ll dropped, ~2^-18).
__global__ void prep_wt(const float* __restrict__ wT) {
    int e = blockIdx.x * 256 + threadIdx.x;    // over 512*256
    int r = e >> 8, c = e & 255;               // r: dim, c: comp
    float v  = wT[e];
    __nv_bfloat16 hi = __float2bfloat16_rn(v);
    __nv_bfloat16 lo = __float2bfloat16_rn(v - __bfloat162float(hi));
    {   // B1 row n=c (comp), k=r (dim); row stride 2*NDIM = 1024
        size_t base = (size_t)c * 1024 + (r >> 4) * 32 + permj(r & 15);
        g_B1[base] = hi; g_B1[base + 16] = lo;
    }
    {   // B2 row n=r (dim), k=c (comp); row stride 2*NCOMP = 512
        size_t base = (size_t)r * 512 + (c >> 4) * 32 + permj(c & 15);
        g_B2[base] = hi; g_B2[base + 16] = lo;
    }
}

// knots [c][j][t] -> [c][t][j]
__global__ void prep_knots(const float* __restrict__ kx, const float* __restrict__ ky,
                           const float* __restrict__ kd) {
    int e = blockIdx.x * 256 + threadIdx.x;    // 8*100*256
    int c = e / (NBIN * NCOMP);
    int rem = e - c * NBIN * NCOMP;
    int t = rem >> 8, j = rem & 255;
    int src = (c * NCOMP + j) * NBIN + t;
    g_ktx[e] = kx[src]; g_kty[e] = ky[src]; g_ktd[e] = kd[src];
}

// class sort
__global__ void prep_zero() {
    if (threadIdx.x < NCLASS) { g_cnt[threadIdx.x] = 0; g_cur[threadIdx.x] = 0; }
}
__global__ void prep_count(const int* __restrict__ label) {
    __shared__ int h[NCLASS];
    if (threadIdx.x < NCLASS) h[threadIdx.x] = 0;
    __syncthreads();
    atomicAdd(&h[label[blockIdx.x * 256 + threadIdx.x]], 1);
    __syncthreads();
    if (threadIdx.x < NCLASS) atomicAdd(&g_cnt[threadIdx.x], h[threadIdx.x]);
}
__global__ void prep_scatter(const int* __restrict__ label) {
    __shared__ int h[NCLASS], base[NCLASS], off[NCLASS];
    if (threadIdx.x < NCLASS) h[threadIdx.x] = 0;
    __syncthreads();
    int i = blockIdx.x * 256 + threadIdx.x;
    int c = label[i];
    int r = atomicAdd(&h[c], 1);               // intra-block rank
    __syncthreads();
    if (threadIdx.x < NCLASS) {
        base[threadIdx.x] = atomicAdd(&g_cur[threadIdx.x], h[threadIdx.x]);
        int o = 0;
        #pragma unroll
        for (int cc = 0; cc < NCLASS; ++cc) if (cc < threadIdx.x) o += g_cnt[cc];
        off[threadIdx.x] = o;
    }
    __syncthreads();
    g_idx[off[c] + base[c] + r] = i;
}

// ---------------- GEMM staging (256 threads, 128x128 CTA tile) --------------
// Row stride stays 48 (96B) for bank-conflict freedom (bank = lr*24+seg*8+lc*2
// is a permutation across lr for seg in {0,16}); cols 32..47 unused.
#define ASTRIDE 48
#define BSTRIDE_S 48
#define NTHR 256

template<int LDA>
__device__ __forceinline__ void ldgA(const float* __restrict__ Ag, int m0, int ci,
                                     int tid, float4* a_src) {
    #pragma unroll
    for (int i = 0; i < 2; ++i) {
        int idx = tid + i * 256;
        int row = idx >> 2, fi = idx & 3;
        a_src[i] = *(const float4*)&Ag[(size_t)(m0 + row) * LDA + ci * 16 + fi * 4];
    }
}
// A: write [hi | lo] segments only
__device__ __forceinline__ void stsA(__nv_bfloat16* __restrict__ Ab, int tid,
                                     const float4* a_src) {
    #pragma unroll
    for (int i = 0; i < 2; ++i) {
        int idx = tid + i * 256;
        int row = idx >> 2, fi = idx & 3;
        const float* v = (const float*)&a_src[i];
        #pragma unroll
        for (int hpair = 0; hpair < 2; ++hpair) {
            int j0 = fi * 4 + hpair * 2;       // even -> permj(j0+1)==permj(j0)+1
            float v0 = v[hpair * 2], v1 = v[hpair * 2 + 1];
            __nv_bfloat16 h0 = __float2bfloat16_rn(v0);
            __nv_bfloat16 h1 = __float2bfloat16_rn(v1);
            __nv_bfloat16 l0 = __float2bfloat16_rn(v0 - __bfloat162float(h0));
            __nv_bfloat16 l1 = __float2bfloat16_rn(v1 - __bfloat162float(h1));
            int p = row * ASTRIDE + permj(j0);
            *(__nv_bfloat162*)&Ab[p]      = __nv_bfloat162(h0, h1);
            *(__nv_bfloat162*)&Ab[p + 16] = __nv_bfloat162(l0, l1);
        }
    }
}
// coalesced: 4 consecutive threads cover one row's 64B chunk (4 x 16B)
template<int BSTR>
__device__ __forceinline__ void cpB(const __nv_bfloat16* __restrict__ Bg, int n0,
                                    int ci, int tid, __nv_bfloat16* __restrict__ Bb) {
    #pragma unroll
    for (int i = 0; i < 2; ++i) {              // 128 rows * 4 = 512 transfers
        int idx = tid + i * 256;
        int row = idx >> 2, f = idx & 3;
        cp16(&Bb[row * BSTRIDE_S + f * 8],
             &Bg[(size_t)(n0 + row) * BSTR + ci * 32 + f * 8]);
    }
}

// ---------------- main GEMM (128x128 CTA, 8 warps, 32x64 warp tile, 2 CTA/SM)
// EPI=1: g_data0[M,256] = data @ wT           (A=data,    B=g_B1, C=g_data0)
// EPI=2: out[M,512]     = data + delta @ wT^T (A=g_data0, B=g_B2, C=out)
template<int NCH, int BSTR, int LDA, int EPI>
__global__ __launch_bounds__(NTHR, 2)
void gemm_k(const float* __restrict__ Adat, const float* __restrict__ Dg,
            float* __restrict__ Cg)
{
    constexpr int NTN = 8;                     // 8 x n8 = 64 cols per warp
    constexpr int MI  = 2;                     // 2 x m16 = 32 rows per warp
    constexpr int ASZ = 128 * ASTRIDE;
    constexpr int BSZ = 128 * BSTRIDE_S;
    constexpr int SSZ = ASZ + BSZ;
    extern __shared__ __nv_bfloat16 smb[];
    __nv_bfloat16* Abuf[2] = { smb, smb + SSZ };
    __nv_bfloat16* Bbuf[2] = { smb + ASZ, smb + SSZ + ASZ };

    const int tid = threadIdx.x, lane = tid & 31, wid = tid >> 5;
    const int lr = lane >> 2, lc = lane & 3;
    const int m0 = blockIdx.x * 128;
    const int n0 = blockIdx.y * 128;
    const int mw = (wid >> 1) * 32;            // 4 warp-rows x 32
    const int nw = (wid & 1) * 64;             // 2 warp-cols x 64

    const float*         Ag = (EPI == 1) ? Adat : (const float*)g_data0;
    const __nv_bfloat16* Bg = (EPI == 1) ? g_B1 : g_B2;
    float*               Cp = (EPI == 1) ? (float*)g_data0 : Cg;

    float acc[MI][NTN][4];
    #pragma unroll
    for (int mi = 0; mi < MI; ++mi)
        #pragma unroll
        for (int ni = 0; ni < NTN; ++ni)
            #pragma unroll
            for (int q = 0; q < 4; ++q) acc[mi][ni][q] = 0.f;

    float4 a_src[2];

    cpB<BSTR>(Bg, n0, 0, tid, Bbuf[0]);
    CP_COMMIT();
    ldgA<LDA>(Ag, m0, 0, tid, a_src);
    stsA(Abuf[0], tid, a_src);
    CP_WAIT0();
    __syncthreads();

    for (int ci = 0; ci < NCH; ++ci) {
        const int cur = ci & 1, nxt = cur ^ 1;
        if (ci + 1 < NCH) {
            cpB<BSTR>(Bg, n0, ci + 1, tid, Bbuf[nxt]);
            CP_COMMIT();
            ldgA<LDA>(Ag, m0, ci + 1, tid, a_src);
        }
        const __nv_bfloat16* Ab = Abuf[cur];
        const __nv_bfloat16* Bb = Bbuf[cur];

        // hoist A hi/lo fragments for the whole chunk
        uint32_t aHf[MI][4], aLf[MI][4];
        #pragma unroll
        for (int mi = 0; mi < MI; ++mi) {
            int ar = mw + mi * 16 + lr;
            uint2 h0 = *(const uint2*)&Ab[ar * ASTRIDE + lc * 4];
            uint2 h1 = *(const uint2*)&Ab[(ar + 8) * ASTRIDE + lc * 4];
            aHf[mi][0] = h0.x; aHf[mi][1] = h1.x; aHf[mi][2] = h0.y; aHf[mi][3] = h1.y;
            uint2 l0 = *(const uint2*)&Ab[ar * ASTRIDE + 16 + lc * 4];
            uint2 l1 = *(const uint2*)&Ab[(ar + 8) * ASTRIDE + 16 + lc * 4];
            aLf[mi][0] = l0.x; aLf[mi][1] = l1.x; aLf[mi][2] = l0.y; aLf[mi][3] = l1.y;
        }

        {   // B hi: aH*bH + aL*bH
            uint2 bf[NTN];
            #pragma unroll
            for (int ni = 0; ni < NTN; ++ni)
                bf[ni] = *(const uint2*)&Bb[(nw + ni * 8 + lr) * BSTRIDE_S + lc * 4];
            #pragma unroll
            for (int mi = 0; mi < MI; ++mi)
                #pragma unroll
                for (int ni = 0; ni < NTN; ++ni)
                    mma16(acc[mi][ni], aHf[mi], (const uint32_t*)&bf[ni]);
            #pragma unroll
            for (int mi = 0; mi < MI; ++mi)
                #pragma unroll
                for (int ni = 0; ni < NTN; ++ni)
                    mma16(acc[mi][ni], aLf[mi], (const uint32_t*)&bf[ni]);
        }
        {   // B lo: aH*bL
            uint2 bf[NTN];
            #pragma unroll
            for (int ni = 0; ni < NTN; ++ni)
                bf[ni] = *(const uint2*)&Bb[(nw + ni * 8 + lr) * BSTRIDE_S + 16 + lc * 4];
            #pragma unroll
            for (int mi = 0; mi < MI; ++mi)
                #pragma unroll
                for (int ni = 0; ni < NTN; ++ni)
                    mma16(acc[mi][ni], aHf[mi], (const uint32_t*)&bf[ni]);
        }

        if (ci + 1 < NCH) { stsA(Abuf[nxt], tid, a_src); CP_WAIT0(); }
        __syncthreads();
    }

    #pragma unroll
    for (int mi = 0; mi < MI; ++mi) {
        int r0 = m0 + mw + mi * 16 + lr;
        #pragma unroll
        for (int ni = 0; ni < NTN; ++ni) {
            int cc = n0 + nw + ni * 8 + 2 * lc;
            if (EPI == 1) {
                *(float2*)&Cp[(size_t)r0 * NCOMP + cc] =
                    make_float2(acc[mi][ni][0], acc[mi][ni][1]);
                *(float2*)&Cp[(size_t)(r0 + 8) * NCOMP + cc] =
                    make_float2(acc[mi][ni][2], acc[mi][ni][3]);
            } else {
                float2 d0 = *(const float2*)&Dg[(size_t)r0 * NDIM + cc];
                float2 d1 = *(const float2*)&Dg[(size_t)(r0 + 8) * NDIM + cc];
                *(float2*)&Cp[(size_t)r0 * NDIM + cc] =
                    make_float2(acc[mi][ni][0] + d0.x, acc[mi][ni][1] + d0.y);
                *(float2*)&Cp[(size_t)(r0 + 8) * NDIM + cc] =
                    make_float2(acc[mi][ni][2] + d1.x, acc[mi][ni][3] + d1.y);
            }
        }
    }
}

// ---------------- spline: class-sorted, smem tables, lane=comp -------------
#define SPB 128                                // blocks per class
__global__ __launch_bounds__(256) void spline_kernel(float* __restrict__ logj)
{
    __shared__ float xs[NBIN * 32], ys[NBIN * 32], ds[NBIN * 32];
    __shared__ float acc_s[1024];
    const int tid = threadIdx.x, lane = tid & 31, wid = tid >> 5;
    const int c = blockIdx.x / SPB, b = blockIdx.x % SPB;
    const int cnt = g_cnt[c];
    int off = 0;
    #pragma unroll
    for (int cc = 0; cc < NCLASS; ++cc) if (cc < c) off += g_cnt[cc];
    const int chunk = (cnt + SPB - 1) / SPB;
    const int s0 = b * chunk;
    const int s1 = min(s0 + chunk, cnt);
    const int nloc = s1 - s0;
    if (nloc <= 0) return;
    for (int i = tid; i < nloc; i += 256) acc_s[i] = 0.f;

    for (int tile = 0; tile < 8; ++tile) {
        __syncthreads();
        const int j0 = tile * 32;
        for (int e = tid; e < NBIN * 32; e += 256) {
            int t = e >> 5, j = e & 31;
            int gi = (c * NBIN + t) * NCOMP + j0 + j;
            xs[e] = g_ktx[gi]; ys[e] = g_kty[gi]; ds[e] = g_ktd[gi];
        }
        __syncthreads();

        for (int i = s0 + wid; i < s1; i += 8) {
            const int s = g_idx[off + i];
            const size_t gi = (size_t)s * NCOMP + j0 + lane;
            const float x = g_data0[gi];
            int id = 0;
            #pragma unroll
            for (int stp = 64; stp >= 1; stp >>= 1) {
                int t = id + stp;
                int ta = min(t, NBIN);
                float kv = xs[(ta - 1) * 32 + lane];
                if (t <= NBIN && kv < x) id = t;
            }
            int k = min(max(id - 1, 0), NBIN - 2);
            float x0 = xs[k * 32 + lane], x1 = xs[(k + 1) * 32 + lane];
            float y0 = ys[k * 32 + lane], y1 = ys[(k + 1) * 32 + lane];
            float da = ds[k * 32 + lane], db = ds[(k + 1) * 32 + lane];
            float w  = x1 - x0, dy = y1 - y0;
            float iw = __fdividef(1.f, w);
            float sv = dy * iw;
            float xi = fminf(fmaxf((x - x0) * iw, 0.f), 1.f);
            float xi1 = 1.f - xi;
            float denom = sv + (da + db - 2.f * sv) * xi * xi1;
            float idn = __fdividef(1.f, denom);
            float y_in = y0 + dy * (sv * xi * xi + da * xi * xi1) * idn;
            float num  = db * xi * xi + 2.f * sv * xi * xi1 + da * xi1 * xi1;
            bool below = (id == 0), above = (id == NBIN);
            float arg = below ? da : (above ? db : sv * sv * num * idn * idn);
            float y   = below ? (y0 + da * (x - x0))
                              : (above ? (y1 + db * (x - x1)) : y_in);
            float ld  = __logf(arg);
            g_data0[gi] = y - x;
            #pragma unroll
            for (int o = 16; o; o >>= 1) ld += __shfl_down_sync(0xFFFFFFFFu, ld, o);
            if (lane == 0) acc_s[i - s0] += ld;
        }
    }
    __syncthreads();
    for (int i = tid; i < nloc; i += 256)
        logj[g_idx[off + s0 + i]] = acc_s[i];
}

// ---------------- launch ----------------------------------------------------
// gemm1 stays the 4th launch -> lands on ncu's capture slot.
extern "C" void kernel_launch(void* const* d_in, const int* in_sizes, int n_in,
                              void* d_out, int out_size) {
    const float* data  = (const float*)d_in[0];
    const float* wT    = (const float*)d_in[1];
    const float* kx    = (const float*)d_in[2];
    const float* ky    = (const float*)d_in[3];
    const float* kd    = (const float*)d_in[4];
    const int*   label = (const int*)d_in[5];

    float* out  = (float*)d_out;                    // (N, NDIM)
    float* logj = out + (size_t)NSAMP * NDIM;       // (N,)

    constexpr int SMG = 2 * (128 * ASTRIDE + 128 * BSTRIDE_S) * 2;  // 48 KB
    cudaFuncSetAttribute((const void*)gemm_k<32, 1024, 512, 1>,
                         cudaFuncAttributeMaxDynamicSharedMemorySize, SMG);
    cudaFuncSetAttribute((const void*)gemm_k<16, 512, 256, 2>,
                         cudaFuncAttributeMaxDynamicSharedMemorySize, SMG);

    prep_wt<<<NDIM * NCOMP / 256, 256>>>(wT);
    prep_knots<<<NCLASS * NBIN * NCOMP / 256, 256>>>(kx, ky, kd);
    prep_zero<<<1, 32>>>();

    gemm_k<32, 1024, 512, 1><<<dim3(NSAMP / 128, NCOMP / 128), NTHR, SMG>>>(
        data, nullptr, nullptr);

    prep_count<<<NSAMP / 256, 256>>>(label);
    prep_scatter<<<NSAMP / 256, 256>>>(label);

    spline_kernel<<<NCLASS * SPB, 256>>>(logj);

    gemm_k<16, 512, 256, 2><<<dim3(NSAMP / 128, NDIM / 128), NTHR, SMG>>>(
        nullptr, data, out);
}